// round 1
// baseline (speedup 1.0000x reference)
#include <cuda_runtime.h>
#include <math.h>

// Problem constants
#define H_    12
#define D_    128
#define NX    2048
#define NY    256
#define S_    2304     // NX + NY
#define DX_   1536
#define DY_   768
#define QKVN  4608     // 3*DX

// ---------------- scratch (static device globals; no allocation) ----------------
__device__ float g_xm  [(size_t)NX * DX_];
__device__ float g_ym  [(size_t)NY * DY_];
__device__ float g_qkvx[(size_t)NX * QKVN];
__device__ float g_qkvy[(size_t)NY * QKVN];
__device__ float g_Q   [(size_t)H_ * S_ * D_];
__device__ float g_K   [(size_t)H_ * S_ * D_];
__device__ float g_V   [(size_t)H_ * S_ * D_];
__device__ float g_S   [(size_t)H_ * S_ * S_];   // 12*2304*2304 fp32 = 255 MB
__device__ float g_O   [(size_t)S_ * DX_];       // attention out, [s][h*128+d]

// ---------------- reductions ----------------
__device__ __forceinline__ float warp_sum(float v) {
    #pragma unroll
    for (int o = 16; o; o >>= 1) v += __shfl_xor_sync(0xffffffffu, v, o);
    return v;
}
__device__ __forceinline__ float warp_max(float v) {
    #pragma unroll
    for (int o = 16; o; o >>= 1) v = fmaxf(v, __shfl_xor_sync(0xffffffffu, v, o));
    return v;
}
__device__ float block_red(float v, float* sbuf, bool ismax) {
    v = ismax ? warp_max(v) : warp_sum(v);
    int w = threadIdx.x >> 5, nw = blockDim.x >> 5;
    if ((threadIdx.x & 31) == 0) sbuf[w] = v;
    __syncthreads();
    if (threadIdx.x < 32) {
        float t = (threadIdx.x < nw) ? sbuf[threadIdx.x] : (ismax ? -1e30f : 0.f);
        t = ismax ? warp_max(t) : warp_sum(t);
        if (threadIdx.x == 0) sbuf[0] = t;
    }
    __syncthreads();
    float r = sbuf[0];
    __syncthreads();
    return r;
}

// ---------------- RMSNorm + modulation: out = rms(x)*(1+scale) ----------------
__global__ void rms_mod(const float* __restrict__ X, const float* __restrict__ sc,
                        float* __restrict__ out, int Dm, float eps) {
    __shared__ float sbuf[32];
    size_t row = blockIdx.x;
    const float* xr = X + row * Dm;
    float* orow = out + row * Dm;
    float ss = 0.f;
    for (int i = threadIdx.x; i < Dm; i += blockDim.x) { float t = xr[i]; ss += t * t; }
    ss = block_red(ss, sbuf, false);
    float r = rsqrtf(ss / (float)Dm + eps);
    for (int i = threadIdx.x; i < Dm; i += blockDim.x)
        orow[i] = xr[i] * r * (1.f + sc[i]);
}

// ---------------- generic batched SGEMM, C = A*B (+bias), optional B^T ----------------
// A: M x K (lda), B: K x N (ldb) row-major  [TB=false]
//                 B: N x K (ldb) row-major  [TB=true]
// C: M x N (ldc). Batched via blockIdx.z with strides sA/sB/sC.
// Requires: M%128==0, N%128==0, K%8==0, 4-aligned leading dims.
template <bool TB>
__global__ __launch_bounds__(256) void sgemm(
    const float* __restrict__ A, const float* __restrict__ B,
    const float* __restrict__ bias, float* __restrict__ C,
    int M, int N, int K, int lda, int ldb, int ldc,
    long sA, long sB, long sC)
{
    constexpr int BM = 128, BN = 128, BK = 8, TM = 8, TN = 8;
    A += (size_t)blockIdx.z * sA;
    B += (size_t)blockIdx.z * sB;
    C += (size_t)blockIdx.z * sC;
    __shared__ float As[BK][BM];
    __shared__ float Bs[BK][BN];
    int tid = threadIdx.x;
    int brow = blockIdx.y * BM, bcol = blockIdx.x * BN;
    int aRow = tid >> 1, aCol = (tid & 1) * 4;         // 128x8 tile, float4
    int tr = tid >> 4, tc = tid & 15;                  // 16x16 thread grid

    float acc[TM][TN];
    #pragma unroll
    for (int i = 0; i < TM; i++)
        #pragma unroll
        for (int j = 0; j < TN; j++) acc[i][j] = 0.f;

    for (int k0 = 0; k0 < K; k0 += BK) {
        float4 av = *(const float4*)(A + (size_t)(brow + aRow) * lda + k0 + aCol);
        As[aCol + 0][aRow] = av.x; As[aCol + 1][aRow] = av.y;
        As[aCol + 2][aRow] = av.z; As[aCol + 3][aRow] = av.w;
        if (TB) {
            float4 bv = *(const float4*)(B + (size_t)(bcol + aRow) * ldb + k0 + aCol);
            Bs[aCol + 0][aRow] = bv.x; Bs[aCol + 1][aRow] = bv.y;
            Bs[aCol + 2][aRow] = bv.z; Bs[aCol + 3][aRow] = bv.w;
        } else {
            int bRow = tid >> 5, bCol = (tid & 31) * 4;
            float4 bv = *(const float4*)(B + (size_t)(k0 + bRow) * ldb + bcol + bCol);
            *(float4*)&Bs[bRow][bCol] = bv;
        }
        __syncthreads();
        #pragma unroll
        for (int kk = 0; kk < BK; kk++) {
            float4 a0 = *(float4*)&As[kk][tr * TM];
            float4 a1 = *(float4*)&As[kk][tr * TM + 4];
            float4 b0 = *(float4*)&Bs[kk][tc * TN];
            float4 b1 = *(float4*)&Bs[kk][tc * TN + 4];
            float ar[8] = {a0.x, a0.y, a0.z, a0.w, a1.x, a1.y, a1.z, a1.w};
            float br[8] = {b0.x, b0.y, b0.z, b0.w, b1.x, b1.y, b1.z, b1.w};
            #pragma unroll
            for (int i = 0; i < TM; i++)
                #pragma unroll
                for (int j = 0; j < TN; j++)
                    acc[i][j] = fmaf(ar[i], br[j], acc[i][j]);
        }
        __syncthreads();
    }
    #pragma unroll
    for (int i = 0; i < TM; i++) {
        int r = brow + tr * TM + i;
        #pragma unroll
        for (int j = 0; j < TN; j += 4) {
            int c = bcol + tc * TN + j;
            float4 v = make_float4(acc[i][j], acc[i][j + 1], acc[i][j + 2], acc[i][j + 3]);
            if (bias) {
                v.x += __ldg(bias + c);     v.y += __ldg(bias + c + 1);
                v.z += __ldg(bias + c + 2); v.w += __ldg(bias + c + 3);
            }
            *(float4*)(C + (size_t)r * ldc + c) = v;
        }
    }
}

// ---------------- per-(token,head) Q/K RMSNorm + weight + RoPE; split into [H][S][D] ----------------
__global__ void qkv_transform(
    const float* __restrict__ rope_cos, const float* __restrict__ rope_sin,
    const float* __restrict__ qnx, const float* __restrict__ knx,
    const float* __restrict__ qny, const float* __restrict__ kny)
{
    __shared__ float sbuf[32];
    int s = blockIdx.x, h = blockIdx.y, d = threadIdx.x;
    bool isx = (s < NX);
    const float* base = isx ? (g_qkvx + (size_t)s * QKVN)
                            : (g_qkvy + (size_t)(s - NX) * QKVN);
    int col = h * D_ + d;
    float q = base[col];
    float k = base[DX_ + col];
    float v = base[2 * DX_ + col];

    float sq = block_red(q * q, sbuf, false);
    float sk = block_red(k * k, sbuf, false);
    float rq = rsqrtf(sq * (1.f / D_) + 1e-5f);
    float rk = rsqrtf(sk * (1.f / D_) + 1e-5f);
    float qn = q * rq * (isx ? qnx[d] : qny[d]);
    float kn = k * rk * (isx ? knx[d] : kny[d]);

    if (isx) {
        int i = d >> 1;
        size_t ridx = ((size_t)s * H_ + h) * (D_ / 2) + i;
        float c  = rope_cos[ridx];
        float sn = rope_sin[ridx];
        float qp = __shfl_xor_sync(0xffffffffu, qn, 1);
        float kp = __shfl_xor_sync(0xffffffffu, kn, 1);
        if ((d & 1) == 0) { qn = qn * c - qp * sn;  kn = kn * c - kp * sn; }
        else              { qn = qp * sn + qn * c;  kn = kp * sn + kn * c; }
    }
    size_t o = ((size_t)h * S_ + s) * D_ + d;
    g_Q[o] = qn; g_K[o] = kn; g_V[o] = v;
}

// ---------------- softmax over rows of scores (scale applied here) ----------------
__global__ void softmax_rows(float* __restrict__ Sm, float scale) {
    const int n = S_;               // 2304 = 9*256
    __shared__ float sbuf[32];
    float* row = Sm + ((size_t)blockIdx.y * n + blockIdx.x) * n;
    float v[9];
    float mx = -1e30f;
    #pragma unroll
    for (int i = 0; i < 9; i++) {
        v[i] = row[threadIdx.x + i * 256];
        mx = fmaxf(mx, v[i]);
    }
    mx = block_red(mx, sbuf, true);
    float sum = 0.f;
    #pragma unroll
    for (int i = 0; i < 9; i++) {
        float e = __expf((v[i] - mx) * scale);
        v[i] = e; sum += e;
    }
    sum = block_red(sum, sbuf, false);
    float inv = 1.f / sum;
    #pragma unroll
    for (int i = 0; i < 9; i++) row[threadIdx.x + i * 256] = v[i] * inv;
}

// ---------------- launch ----------------
extern "C" void kernel_launch(void* const* d_in, const int* in_sizes, int n_in,
                              void* d_out, int out_size)
{
    const float* x        = (const float*)d_in[0];
    const float* y        = (const float*)d_in[1];
    const float* scale_x  = (const float*)d_in[2];
    const float* scale_y  = (const float*)d_in[3];
    const float* rope_cos = (const float*)d_in[4];
    const float* rope_sin = (const float*)d_in[5];
    const float* Wqkv_x   = (const float*)d_in[6];
    const float* bqkv_x   = (const float*)d_in[7];
    const float* Wqkv_y   = (const float*)d_in[8];
    const float* bqkv_y   = (const float*)d_in[9];
    const float* q_norm_x = (const float*)d_in[10];
    const float* k_norm_x = (const float*)d_in[11];
    const float* q_norm_y = (const float*)d_in[12];
    const float* k_norm_y = (const float*)d_in[13];
    const float* Wproj_x  = (const float*)d_in[14];
    const float* bproj_x  = (const float*)d_in[15];
    const float* Wproj_y  = (const float*)d_in[16];
    const float* bproj_y  = (const float*)d_in[17];
    float* out = (float*)d_out;

    float *xm, *ym, *qkvx, *qkvy, *Q, *K, *V, *Sc, *O;
    cudaGetSymbolAddress((void**)&xm,   g_xm);
    cudaGetSymbolAddress((void**)&ym,   g_ym);
    cudaGetSymbolAddress((void**)&qkvx, g_qkvx);
    cudaGetSymbolAddress((void**)&qkvy, g_qkvy);
    cudaGetSymbolAddress((void**)&Q,    g_Q);
    cudaGetSymbolAddress((void**)&K,    g_K);
    cudaGetSymbolAddress((void**)&V,    g_V);
    cudaGetSymbolAddress((void**)&Sc,   g_S);
    cudaGetSymbolAddress((void**)&O,    g_O);

    // 1) modulated RMSNorm
    rms_mod<<<NX, 256>>>(x, scale_x, xm, DX_, 1e-6f);
    rms_mod<<<NY, 256>>>(y, scale_y, ym, DY_, 1e-6f);

    // 2) QKV projections
    sgemm<false><<<dim3(QKVN / 128, NX / 128, 1), 256>>>(
        xm, Wqkv_x, bqkv_x, qkvx, NX, QKVN, DX_, DX_, QKVN, QKVN, 0, 0, 0);
    sgemm<false><<<dim3(QKVN / 128, NY / 128, 1), 256>>>(
        ym, Wqkv_y, bqkv_y, qkvy, NY, QKVN, DY_, DY_, QKVN, QKVN, 0, 0, 0);

    // 3) per-head Q/K RMSNorm + RoPE, layout [H][S][D]
    qkv_transform<<<dim3(S_, H_), D_>>>(rope_cos, rope_sin,
                                        q_norm_x, k_norm_x, q_norm_y, k_norm_y);

    // 4) scores = Q @ K^T  (batched over heads)
    sgemm<true><<<dim3(S_ / 128, S_ / 128, H_), 256>>>(
        Q, K, nullptr, Sc, S_, S_, D_, D_, D_, S_,
        (long)S_ * D_, (long)S_ * D_, (long)S_ * S_);

    // 5) softmax (scale 1/sqrt(128) fused)
    softmax_rows<<<dim3(S_, H_), 256>>>(Sc, 0.08838834764831845f);

    // 6) O = P @ V, written directly in [s][h*128+d] layout (ldc=DX, batch C-stride=D)
    sgemm<false><<<dim3(1, S_ / 128, H_), 256>>>(
        Sc, V, nullptr, O, S_, D_, S_, S_, D_, DX_,
        (long)S_ * S_, (long)S_ * D_, (long)D_);

    // 7) output projections straight into d_out
    sgemm<false><<<dim3(DX_ / 128, NX / 128, 1), 256>>>(
        O, Wproj_x, bproj_x, out, NX, DX_, DX_, DX_, DX_, DX_, 0, 0, 0);
    sgemm<false><<<dim3(DY_ / 128, NY / 128, 1), 256>>>(
        O + (size_t)NX * DX_, Wproj_y, bproj_y, out + (size_t)NX * DX_,
        NY, DY_, DX_, DX_, DY_, DY_, 0, 0, 0);
}

// round 3
// speedup vs baseline: 2.2706x; 2.2706x over previous
#include <cuda_runtime.h>
#include <cuda_bf16.h>
#include <cstdint>
#include <math.h>

#define H_    12
#define D_    128
#define NX    2048
#define NY    256
#define S_    2304
#define DX_   1536
#define DY_   768
#define QKVN  4608

typedef __nv_bfloat16 bf16;

// ---------------- scratch (static device globals; no allocation) ----------------
__device__ __align__(256) float g_qkvx[(size_t)NX * QKVN];
__device__ __align__(256) float g_qkvy[(size_t)NY * QKVN];
__device__ __align__(256) float g_S   [(size_t)H_ * S_ * S_];     // 255 MB scores
__device__ __align__(256) bf16 g_xm_h[(size_t)NX * DX_],  g_xm_l[(size_t)NX * DX_];
__device__ __align__(256) bf16 g_ym_h[(size_t)NY * DY_],  g_ym_l[(size_t)NY * DY_];
__device__ __align__(256) bf16 g_WqxT_h[(size_t)QKVN * DX_], g_WqxT_l[(size_t)QKVN * DX_];
__device__ __align__(256) bf16 g_WqyT_h[(size_t)QKVN * DY_], g_WqyT_l[(size_t)QKVN * DY_];
__device__ __align__(256) bf16 g_WpxT_h[(size_t)DX_ * DX_],  g_WpxT_l[(size_t)DX_ * DX_];
__device__ __align__(256) bf16 g_WpyT_h[(size_t)DY_ * DX_],  g_WpyT_l[(size_t)DY_ * DX_];
__device__ __align__(256) bf16 g_Qh[(size_t)H_ * S_ * D_], g_Ql[(size_t)H_ * S_ * D_];
__device__ __align__(256) bf16 g_Kh[(size_t)H_ * S_ * D_], g_Kl[(size_t)H_ * S_ * D_];
__device__ __align__(256) bf16 g_Vth[(size_t)H_ * D_ * S_], g_Vtl[(size_t)H_ * D_ * S_];
__device__ __align__(256) bf16 g_Ph[(size_t)H_ * S_ * S_],  g_Pl[(size_t)H_ * S_ * S_];
__device__ __align__(256) bf16 g_Oh[(size_t)S_ * DX_],      g_Ol[(size_t)S_ * DX_];

// ---------------- small helpers ----------------
__device__ __forceinline__ float warp_sum(float v) {
    #pragma unroll
    for (int o = 16; o; o >>= 1) v += __shfl_xor_sync(0xffffffffu, v, o);
    return v;
}
__device__ __forceinline__ float warp_max(float v) {
    #pragma unroll
    for (int o = 16; o; o >>= 1) v = fmaxf(v, __shfl_xor_sync(0xffffffffu, v, o));
    return v;
}
__device__ float block_red(float v, float* sbuf, bool ismax) {
    v = ismax ? warp_max(v) : warp_sum(v);
    int w = threadIdx.x >> 5, nw = blockDim.x >> 5;
    if ((threadIdx.x & 31) == 0) sbuf[w] = v;
    __syncthreads();
    if (threadIdx.x < 32) {
        float t = (threadIdx.x < nw) ? sbuf[threadIdx.x] : (ismax ? -1e30f : 0.f);
        t = ismax ? warp_max(t) : warp_sum(t);
        if (threadIdx.x == 0) sbuf[0] = t;
    }
    __syncthreads();
    float r = sbuf[0];
    __syncthreads();
    return r;
}
__device__ __forceinline__ void split_bf16(float v, bf16& h, bf16& l) {
    h = __float2bfloat16(v);
    l = __float2bfloat16(v - __bfloat162float(h));
}
__device__ __forceinline__ uint32_t smem_u32(const void* p) {
    return (uint32_t)__cvta_generic_to_shared(p);
}
__device__ __forceinline__ void cp16(uint32_t s, const void* g) {
    asm volatile("cp.async.cg.shared.global [%0], [%1], 16;" :: "r"(s), "l"(g));
}
__device__ __forceinline__ void ldmx4(uint32_t* r, uint32_t a) {
    asm volatile("ldmatrix.sync.aligned.m8n8.x4.shared.b16 {%0,%1,%2,%3}, [%4];"
                 : "=r"(r[0]), "=r"(r[1]), "=r"(r[2]), "=r"(r[3]) : "r"(a));
}
__device__ __forceinline__ void mma16816(float* c, const uint32_t* a, uint32_t b0, uint32_t b1) {
    asm volatile(
        "mma.sync.aligned.m16n8k16.row.col.f32.bf16.bf16.f32 "
        "{%0,%1,%2,%3}, {%4,%5,%6,%7}, {%8,%9}, {%0,%1,%2,%3};"
        : "+f"(c[0]), "+f"(c[1]), "+f"(c[2]), "+f"(c[3])
        : "r"(a[0]), "r"(a[1]), "r"(a[2]), "r"(a[3]), "r"(b0), "r"(b1));
}

// ---------------- bf16x3 HMMA GEMM ----------------
// C[128x128] per CTA. A: (M x K) K-major hi/lo. B: (N x K) K-major hi/lo.
// grid = (N/128, M/128, batch). K % 32 == 0, K >= 64.
#define PADB   80                      // bytes per smem row (32 bf16 + 8 pad)
#define TILEB  (128 * PADB)            // 10240
#define STAGEB (4 * TILEB)             // 40960
#define GSMEM  (2 * STAGEB)            // 81920

__global__ __launch_bounds__(256, 1)
void mma_gemm(const bf16* __restrict__ Ah, const bf16* __restrict__ Al,
              const bf16* __restrict__ Bh, const bf16* __restrict__ Bl,
              const float* __restrict__ bias,
              float* __restrict__ Cf, bf16* __restrict__ Ch, bf16* __restrict__ Cl,
              int K, int lda, int ldb, int ldc,
              long sA, long sB, long sC)
{
    extern __shared__ char smem[];
    uint32_t sb = smem_u32(smem);
    int tid = threadIdx.x, wid = tid >> 5, lane = tid & 31;
    int wr = wid >> 1, wc = wid & 1;

    const bf16* pAh = Ah + (size_t)blockIdx.z * sA + (size_t)blockIdx.y * 128 * lda;
    const bf16* pAl = Al + (size_t)blockIdx.z * sA + (size_t)blockIdx.y * 128 * lda;
    const bf16* pBh = Bh + (size_t)blockIdx.z * sB + (size_t)blockIdx.x * 128 * ldb;
    const bf16* pBl = Bl + (size_t)blockIdx.z * sB + (size_t)blockIdx.x * 128 * ldb;

    const int NC = K >> 5;             // chunks of 32

    // stage loader: 4 tiles of [128 rows x 32 bf16]
    auto load_stage = [&](int st, int k0) {
        uint32_t s0 = sb + st * STAGEB;
        const bf16* srcs[4] = {pAh, pAl, pBh, pBl};
        #pragma unroll
        for (int t = 0; t < 4; t++) {
            int ldt = (t < 2) ? lda : ldb;
            const char* gb = (const char*)srcs[t] + (size_t)k0 * 2;
            #pragma unroll
            for (int i = 0; i < 2; i++) {
                int idx = tid + (i << 8);
                int row = idx >> 2, ch = idx & 3;
                cp16(s0 + t * TILEB + row * PADB + ch * 16,
                     gb + (size_t)row * ldt * 2 + ch * 16);
            }
        }
        asm volatile("cp.async.commit_group;");
    };

    float acc[2][8][4];
    #pragma unroll
    for (int i = 0; i < 2; i++)
        #pragma unroll
        for (int j = 0; j < 8; j++)
            #pragma unroll
            for (int r = 0; r < 4; r++) acc[i][j][r] = 0.f;

    int r8 = lane & 7, seg = lane >> 3;
    int a_row = (seg & 1) * 8 + r8;         // within m16
    int a_kb  = (seg >> 1) * 16;            // byte offset within k16
    int b_row = (seg >> 1) * 8 + r8;        // within n16
    int b_kb  = (seg & 1) * 16;

    load_stage(0, 0);

    for (int i = 0; i < NC; i++) {
        if (i + 1 < NC) {
            load_stage((i + 1) & 1, (i + 1) << 5);
            asm volatile("cp.async.wait_group 1;");
        } else {
            asm volatile("cp.async.wait_group 0;");
        }
        __syncthreads();

        uint32_t base = sb + (i & 1) * STAGEB;
        #pragma unroll
        for (int ks = 0; ks < 2; ks++) {
            int kb = ks * 32;
            uint32_t ah[2][4], al[2][4], bh[4][4], bl[4][4];
            #pragma unroll
            for (int mi = 0; mi < 2; mi++) {
                uint32_t ad = base + (wr * 32 + mi * 16 + a_row) * PADB + kb + a_kb;
                ldmx4(ah[mi], ad);
                ldmx4(al[mi], ad + TILEB);
            }
            #pragma unroll
            for (int nj = 0; nj < 4; nj++) {
                uint32_t bd = base + 2 * TILEB + (wc * 64 + nj * 16 + b_row) * PADB + kb + b_kb;
                ldmx4(bh[nj], bd);
                ldmx4(bl[nj], bd + TILEB);
            }
            #pragma unroll
            for (int mi = 0; mi < 2; mi++)
                #pragma unroll
                for (int nt = 0; nt < 8; nt++) {
                    int nj = nt >> 1, hf = (nt & 1) * 2;
                    mma16816(acc[mi][nt], ah[mi], bh[nj][hf], bh[nj][hf + 1]);
                    mma16816(acc[mi][nt], ah[mi], bl[nj][hf], bl[nj][hf + 1]);
                    mma16816(acc[mi][nt], al[mi], bh[nj][hf], bh[nj][hf + 1]);
                }
        }
        __syncthreads();
    }

    // epilogue: direct stores from fragments
    int brow = blockIdx.y * 128 + wr * 32 + (lane >> 2);
    int bcol = blockIdx.x * 128 + wc * 64 + (lane & 3) * 2;
    #pragma unroll
    for (int mi = 0; mi < 2; mi++)
        #pragma unroll
        for (int nt = 0; nt < 8; nt++)
            #pragma unroll
            for (int rh = 0; rh < 2; rh++) {
                int rr = brow + mi * 16 + rh * 8;
                int cc = bcol + nt * 8;
                float v0 = acc[mi][nt][rh * 2 + 0];
                float v1 = acc[mi][nt][rh * 2 + 1];
                if (bias) { v0 += __ldg(bias + cc); v1 += __ldg(bias + cc + 1); }
                size_t ci = (size_t)blockIdx.z * sC + (size_t)rr * ldc + cc;
                if (Cf) *(float2*)(Cf + ci) = make_float2(v0, v1);
                if (Ch) {
                    bf16 h0, l0, h1, l1;
                    split_bf16(v0, h0, l0); split_bf16(v1, h1, l1);
                    *(__nv_bfloat162*)(Ch + ci) = __nv_bfloat162(h0, h1);
                    *(__nv_bfloat162*)(Cl + ci) = __nv_bfloat162(l0, l1);
                }
            }
}

// ---------------- RMSNorm + modulation, split hi/lo ----------------
__global__ void rms_mod_split(const float* __restrict__ X, const float* __restrict__ sc,
                              bf16* __restrict__ oh, bf16* __restrict__ ol, int Dm, float eps) {
    __shared__ float sbuf[32];
    size_t row = blockIdx.x;
    const float* xr = X + row * Dm;
    float ss = 0.f;
    for (int i = threadIdx.x; i < Dm; i += blockDim.x) { float t = xr[i]; ss += t * t; }
    ss = block_red(ss, sbuf, false);
    float r = rsqrtf(ss / (float)Dm + eps);
    for (int i = threadIdx.x; i < Dm; i += blockDim.x) {
        float v = xr[i] * r * (1.f + sc[i]);
        bf16 h, l; split_bf16(v, h, l);
        oh[row * Dm + i] = h; ol[row * Dm + i] = l;
    }
}

// ---------------- weight transpose + split: W[K x N] -> T[N x K] hi/lo ----------------
__global__ void wconv(const float* __restrict__ W, bf16* __restrict__ Th, bf16* __restrict__ Tl,
                      int K, int N) {
    __shared__ float t[32][33];
    int n0 = blockIdx.x * 32, k0 = blockIdx.y * 32;
    int tx = threadIdx.x, ty = threadIdx.y;
    #pragma unroll
    for (int j = 0; j < 32; j += 8)
        t[ty + j][tx] = W[(size_t)(k0 + ty + j) * N + n0 + tx];
    __syncthreads();
    #pragma unroll
    for (int j = 0; j < 32; j += 8) {
        float v = t[tx][ty + j];
        size_t o = (size_t)(n0 + ty + j) * K + k0 + tx;
        bf16 h, l; split_bf16(v, h, l);
        Th[o] = h; Tl[o] = l;
    }
}

// ---------------- Q/K per-head RMSNorm + RoPE, split into [H][S][D] hi/lo ----------------
__global__ void qkv_transform(const float* __restrict__ rope_cos, const float* __restrict__ rope_sin,
                              const float* __restrict__ qnx, const float* __restrict__ knx,
                              const float* __restrict__ qny, const float* __restrict__ kny) {
    __shared__ float sbuf[32];
    int s = blockIdx.x, h = blockIdx.y, d = threadIdx.x;
    bool isx = (s < NX);
    const float* base = isx ? (g_qkvx + (size_t)s * QKVN) : (g_qkvy + (size_t)(s - NX) * QKVN);
    int col = h * D_ + d;
    float q = base[col];
    float k = base[DX_ + col];

    float sq = block_red(q * q, sbuf, false);
    float sk = block_red(k * k, sbuf, false);
    float rq = rsqrtf(sq * (1.f / D_) + 1e-5f);
    float rk = rsqrtf(sk * (1.f / D_) + 1e-5f);
    float qn = q * rq * (isx ? qnx[d] : qny[d]);
    float kn = k * rk * (isx ? knx[d] : kny[d]);

    if (isx) {
        int i = d >> 1;
        size_t ridx = ((size_t)s * H_ + h) * (D_ / 2) + i;
        float c = rope_cos[ridx];
        float sn = rope_sin[ridx];
        float qp = __shfl_xor_sync(0xffffffffu, qn, 1);
        float kp = __shfl_xor_sync(0xffffffffu, kn, 1);
        if ((d & 1) == 0) { qn = qn * c - qp * sn;  kn = kn * c - kp * sn; }
        else              { qn = qp * sn + qn * c;  kn = kp * sn + kn * c; }
    }
    size_t o = ((size_t)h * S_ + s) * D_ + d;
    bf16 hh, ll;
    split_bf16(qn, hh, ll); g_Qh[o] = hh; g_Ql[o] = ll;
    split_bf16(kn, hh, ll); g_Kh[o] = hh; g_Kl[o] = ll;
}

// ---------------- V: gather from qkv fp32, transpose to [H][D][S], split ----------------
__global__ void vconv() {
    __shared__ float t[32][33];
    int s0 = blockIdx.x * 32, d0 = blockIdx.y * 32, h = blockIdx.z;
    int tx = threadIdx.x, ty = threadIdx.y;
    #pragma unroll
    for (int j = 0; j < 32; j += 8) {
        int s = s0 + ty + j;
        const float* base = (s < NX) ? (g_qkvx + (size_t)s * QKVN)
                                     : (g_qkvy + (size_t)(s - NX) * QKVN);
        t[ty + j][tx] = base[2 * DX_ + h * D_ + d0 + tx];
    }
    __syncthreads();
    #pragma unroll
    for (int j = 0; j < 32; j += 8) {
        float v = t[tx][ty + j];
        size_t o = ((size_t)h * D_ + d0 + ty + j) * S_ + s0 + tx;
        bf16 hh, ll; split_bf16(v, hh, ll);
        g_Vth[o] = hh; g_Vtl[o] = ll;
    }
}

// ---------------- softmax rows -> P hi/lo bf16 ----------------
__global__ void softmax_rows(const float* __restrict__ Sm, bf16* __restrict__ Ph,
                             bf16* __restrict__ Pl, float scale) {
    __shared__ float sbuf[32];
    size_t off = ((size_t)blockIdx.y * S_ + blockIdx.x) * S_;
    const float* row = Sm + off;
    float v[9];
    float mx = -1e30f;
    #pragma unroll
    for (int i = 0; i < 9; i++) {
        v[i] = row[threadIdx.x + i * 256];
        mx = fmaxf(mx, v[i]);
    }
    mx = block_red(mx, sbuf, true);
    float sum = 0.f;
    #pragma unroll
    for (int i = 0; i < 9; i++) {
        float e = __expf((v[i] - mx) * scale);
        v[i] = e; sum += e;
    }
    sum = block_red(sum, sbuf, false);
    float inv = 1.f / sum;
    #pragma unroll
    for (int i = 0; i < 9; i++) {
        float p = v[i] * inv;
        bf16 h, l; split_bf16(p, h, l);
        Ph[off + threadIdx.x + i * 256] = h;
        Pl[off + threadIdx.x + i * 256] = l;
    }
}

// ---------------- launch ----------------
extern "C" void kernel_launch(void* const* d_in, const int* in_sizes, int n_in,
                              void* d_out, int out_size)
{
    const float* x        = (const float*)d_in[0];
    const float* y        = (const float*)d_in[1];
    const float* scale_x  = (const float*)d_in[2];
    const float* scale_y  = (const float*)d_in[3];
    const float* rope_cos = (const float*)d_in[4];
    const float* rope_sin = (const float*)d_in[5];
    const float* Wqkv_x   = (const float*)d_in[6];
    const float* bqkv_x   = (const float*)d_in[7];
    const float* Wqkv_y   = (const float*)d_in[8];
    const float* bqkv_y   = (const float*)d_in[9];
    const float* q_norm_x = (const float*)d_in[10];
    const float* k_norm_x = (const float*)d_in[11];
    const float* q_norm_y = (const float*)d_in[12];
    const float* k_norm_y = (const float*)d_in[13];
    const float* Wproj_x  = (const float*)d_in[14];
    const float* bproj_x  = (const float*)d_in[15];
    const float* Wproj_y  = (const float*)d_in[16];
    const float* bproj_y  = (const float*)d_in[17];
    float* out = (float*)d_out;

    cudaFuncSetAttribute(mma_gemm, cudaFuncAttributeMaxDynamicSharedMemorySize, GSMEM);

    float *qkvx, *qkvy, *Sc;
    bf16 *xmh, *xml, *ymh, *yml, *wqxh, *wqxl, *wqyh, *wqyl, *wpxh, *wpxl, *wpyh, *wpyl;
    bf16 *Qh, *Ql, *Kh, *Kl, *Vth, *Vtl, *Ph, *Pl, *Oh, *Ol;
    cudaGetSymbolAddress((void**)&qkvx, g_qkvx);
    cudaGetSymbolAddress((void**)&qkvy, g_qkvy);
    cudaGetSymbolAddress((void**)&Sc,   g_S);
    cudaGetSymbolAddress((void**)&xmh,  g_xm_h);  cudaGetSymbolAddress((void**)&xml, g_xm_l);
    cudaGetSymbolAddress((void**)&ymh,  g_ym_h);  cudaGetSymbolAddress((void**)&yml, g_ym_l);
    cudaGetSymbolAddress((void**)&wqxh, g_WqxT_h); cudaGetSymbolAddress((void**)&wqxl, g_WqxT_l);
    cudaGetSymbolAddress((void**)&wqyh, g_WqyT_h); cudaGetSymbolAddress((void**)&wqyl, g_WqyT_l);
    cudaGetSymbolAddress((void**)&wpxh, g_WpxT_h); cudaGetSymbolAddress((void**)&wpxl, g_WpxT_l);
    cudaGetSymbolAddress((void**)&wpyh, g_WpyT_h); cudaGetSymbolAddress((void**)&wpyl, g_WpyT_l);
    cudaGetSymbolAddress((void**)&Qh, g_Qh);   cudaGetSymbolAddress((void**)&Ql, g_Ql);
    cudaGetSymbolAddress((void**)&Kh, g_Kh);   cudaGetSymbolAddress((void**)&Kl, g_Kl);
    cudaGetSymbolAddress((void**)&Vth, g_Vth); cudaGetSymbolAddress((void**)&Vtl, g_Vtl);
    cudaGetSymbolAddress((void**)&Ph, g_Ph);   cudaGetSymbolAddress((void**)&Pl, g_Pl);
    cudaGetSymbolAddress((void**)&Oh, g_Oh);   cudaGetSymbolAddress((void**)&Ol, g_Ol);

    dim3 t328(32, 8);

    // 1) modulated RMSNorm (split) + weight transpose/split
    rms_mod_split<<<NX, 256>>>(x, scale_x, xmh, xml, DX_, 1e-6f);
    rms_mod_split<<<NY, 256>>>(y, scale_y, ymh, yml, DY_, 1e-6f);
    wconv<<<dim3(QKVN / 32, DX_ / 32), t328>>>(Wqkv_x, wqxh, wqxl, DX_, QKVN);
    wconv<<<dim3(QKVN / 32, DY_ / 32), t328>>>(Wqkv_y, wqyh, wqyl, DY_, QKVN);
    wconv<<<dim3(DX_ / 32,  DX_ / 32), t328>>>(Wproj_x, wpxh, wpxl, DX_, DX_);
    wconv<<<dim3(DY_ / 32,  DX_ / 32), t328>>>(Wproj_y, wpyh, wpyl, DX_, DY_);

    // 2) QKV projections (HMMA)
    mma_gemm<<<dim3(QKVN / 128, NX / 128, 1), 256, GSMEM>>>(
        xmh, xml, wqxh, wqxl, bqkv_x, qkvx, nullptr, nullptr,
        DX_, DX_, DX_, QKVN, 0, 0, 0);
    mma_gemm<<<dim3(QKVN / 128, NY / 128, 1), 256, GSMEM>>>(
        ymh, yml, wqyh, wqyl, bqkv_y, qkvy, nullptr, nullptr,
        DY_, DY_, DY_, QKVN, 0, 0, 0);

    // 3) Q/K transform + V transpose/split
    qkv_transform<<<dim3(S_, H_), D_>>>(rope_cos, rope_sin,
                                        q_norm_x, k_norm_x, q_norm_y, k_norm_y);
    vconv<<<dim3(S_ / 32, D_ / 32, H_), t328>>>();

    // 4) scores = Q @ K^T (batched over heads)
    mma_gemm<<<dim3(S_ / 128, S_ / 128, H_), 256, GSMEM>>>(
        Qh, Ql, Kh, Kl, nullptr, Sc, nullptr, nullptr,
        D_, D_, D_, S_, (long)S_ * D_, (long)S_ * D_, (long)S_ * S_);

    // 5) softmax -> P hi/lo
    softmax_rows<<<dim3(S_, H_), 256>>>(Sc, Ph, Pl, 0.08838834764831845f);

    // 6) O = P @ V -> hi/lo at [s][h*128+d]
    mma_gemm<<<dim3(1, S_ / 128, H_), 256, GSMEM>>>(
        Ph, Pl, Vth, Vtl, nullptr, nullptr, Oh, Ol,
        S_, S_, S_, DX_, (long)S_ * S_, (long)D_ * S_, 128);

    // 7) output projections straight into d_out
    mma_gemm<<<dim3(DX_ / 128, NX / 128, 1), 256, GSMEM>>>(
        Oh, Ol, wpxh, wpxl, bproj_x, out, nullptr, nullptr,
        DX_, DX_, DX_, DX_, 0, 0, 0);
    mma_gemm<<<dim3(DY_ / 128, NY / 128, 1), 256, GSMEM>>>(
        Oh + (size_t)NX * DX_, Ol + (size_t)NX * DX_, wpyh, wpyl, bproj_y,
        out + (size_t)NX * DX_, nullptr, nullptr,
        DX_, DX_, DX_, DY_, 0, 0, 0);
}

// round 4
// speedup vs baseline: 2.7507x; 1.2114x over previous
#include <cuda_runtime.h>
#include <cuda_bf16.h>
#include <cstdint>
#include <math.h>

#define H_    12
#define D_    128
#define NX    2048
#define NY    256
#define S_    2304
#define DX_   1536
#define DY_   768
#define QKVN  4608

typedef __nv_bfloat16 bf16;

// ---------------- scratch (static device globals; no allocation) ----------------
__device__ __align__(256) float g_qkvx[(size_t)NX * QKVN];
__device__ __align__(256) float g_qkvy[(size_t)NY * QKVN];
__device__ __align__(256) bf16 g_xm_h[(size_t)NX * DX_],  g_xm_l[(size_t)NX * DX_];
__device__ __align__(256) bf16 g_ym_h[(size_t)NY * DY_],  g_ym_l[(size_t)NY * DY_];
__device__ __align__(256) bf16 g_WqxT_h[(size_t)QKVN * DX_], g_WqxT_l[(size_t)QKVN * DX_];
__device__ __align__(256) bf16 g_WqyT_h[(size_t)QKVN * DY_], g_WqyT_l[(size_t)QKVN * DY_];
__device__ __align__(256) bf16 g_WpxT_h[(size_t)DX_ * DX_],  g_WpxT_l[(size_t)DX_ * DX_];
__device__ __align__(256) bf16 g_WpyT_h[(size_t)DY_ * DX_],  g_WpyT_l[(size_t)DY_ * DX_];
__device__ __align__(256) bf16 g_Qh[(size_t)H_ * S_ * D_], g_Ql[(size_t)H_ * S_ * D_];
__device__ __align__(256) bf16 g_Kh[(size_t)H_ * S_ * D_], g_Kl[(size_t)H_ * S_ * D_];
__device__ __align__(256) bf16 g_Vth[(size_t)H_ * D_ * S_], g_Vtl[(size_t)H_ * D_ * S_];
__device__ __align__(256) bf16 g_Oh[(size_t)S_ * DX_],      g_Ol[(size_t)S_ * DX_];

// ---------------- small helpers ----------------
__device__ __forceinline__ float warp_sum(float v) {
    #pragma unroll
    for (int o = 16; o; o >>= 1) v += __shfl_xor_sync(0xffffffffu, v, o);
    return v;
}
__device__ __forceinline__ float warp_max(float v) {
    #pragma unroll
    for (int o = 16; o; o >>= 1) v = fmaxf(v, __shfl_xor_sync(0xffffffffu, v, o));
    return v;
}
__device__ float block_red(float v, float* sbuf, bool ismax) {
    v = ismax ? warp_max(v) : warp_sum(v);
    int w = threadIdx.x >> 5, nw = blockDim.x >> 5;
    if ((threadIdx.x & 31) == 0) sbuf[w] = v;
    __syncthreads();
    if (threadIdx.x < 32) {
        float t = (threadIdx.x < nw) ? sbuf[threadIdx.x] : (ismax ? -1e30f : 0.f);
        t = ismax ? warp_max(t) : warp_sum(t);
        if (threadIdx.x == 0) sbuf[0] = t;
    }
    __syncthreads();
    float r = sbuf[0];
    __syncthreads();
    return r;
}
__device__ __forceinline__ void split_bf16(float v, bf16& h, bf16& l) {
    h = __float2bfloat16(v);
    l = __float2bfloat16(v - __bfloat162float(h));
}
__device__ __forceinline__ uint32_t pack_hi2(float a, float b, uint32_t& lo) {
    bf16 h0, l0, h1, l1;
    split_bf16(a, h0, l0); split_bf16(b, h1, l1);
    __nv_bfloat162 hp(h0, h1), lp(l0, l1);
    lo = *(uint32_t*)&lp;
    return *(uint32_t*)&hp;
}
__device__ __forceinline__ uint32_t smem_u32(const void* p) {
    return (uint32_t)__cvta_generic_to_shared(p);
}
__device__ __forceinline__ void cp16(uint32_t s, const void* g) {
    asm volatile("cp.async.cg.shared.global [%0], [%1], 16;" :: "r"(s), "l"(g));
}
__device__ __forceinline__ void ldmx4(uint32_t* r, uint32_t a) {
    asm volatile("ldmatrix.sync.aligned.m8n8.x4.shared.b16 {%0,%1,%2,%3}, [%4];"
                 : "=r"(r[0]), "=r"(r[1]), "=r"(r[2]), "=r"(r[3]) : "r"(a));
}
__device__ __forceinline__ void mma16816(float* c, const uint32_t* a, uint32_t b0, uint32_t b1) {
    asm volatile(
        "mma.sync.aligned.m16n8k16.row.col.f32.bf16.bf16.f32 "
        "{%0,%1,%2,%3}, {%4,%5,%6,%7}, {%8,%9}, {%0,%1,%2,%3};"
        : "+f"(c[0]), "+f"(c[1]), "+f"(c[2]), "+f"(c[3])
        : "r"(a[0]), "r"(a[1]), "r"(a[2]), "r"(a[3]), "r"(b0), "r"(b1));
}

// ---------------- bf16x3 HMMA GEMM (QKV + proj) ----------------
#define PADB   80
#define TILEB  (128 * PADB)
#define STAGEB (4 * TILEB)
#define GSMEM  (2 * STAGEB)

__global__ __launch_bounds__(256, 1)
void mma_gemm(const bf16* __restrict__ Ah, const bf16* __restrict__ Al,
              const bf16* __restrict__ Bh, const bf16* __restrict__ Bl,
              const float* __restrict__ bias,
              float* __restrict__ Cf, bf16* __restrict__ Ch, bf16* __restrict__ Cl,
              int K, int lda, int ldb, int ldc,
              long sA, long sB, long sC)
{
    extern __shared__ char smem[];
    uint32_t sb = smem_u32(smem);
    int tid = threadIdx.x, wid = tid >> 5, lane = tid & 31;
    int wr = wid >> 1, wc = wid & 1;

    const bf16* pAh = Ah + (size_t)blockIdx.z * sA + (size_t)blockIdx.y * 128 * lda;
    const bf16* pAl = Al + (size_t)blockIdx.z * sA + (size_t)blockIdx.y * 128 * lda;
    const bf16* pBh = Bh + (size_t)blockIdx.z * sB + (size_t)blockIdx.x * 128 * ldb;
    const bf16* pBl = Bl + (size_t)blockIdx.z * sB + (size_t)blockIdx.x * 128 * ldb;

    const int NC = K >> 5;

    auto load_stage = [&](int st, int k0) {
        uint32_t s0 = sb + st * STAGEB;
        const bf16* srcs[4] = {pAh, pAl, pBh, pBl};
        #pragma unroll
        for (int t = 0; t < 4; t++) {
            int ldt = (t < 2) ? lda : ldb;
            const char* gb = (const char*)srcs[t] + (size_t)k0 * 2;
            #pragma unroll
            for (int i = 0; i < 2; i++) {
                int idx = tid + (i << 8);
                int row = idx >> 2, ch = idx & 3;
                cp16(s0 + t * TILEB + row * PADB + ch * 16,
                     gb + (size_t)row * ldt * 2 + ch * 16);
            }
        }
        asm volatile("cp.async.commit_group;");
    };

    float acc[2][8][4];
    #pragma unroll
    for (int i = 0; i < 2; i++)
        #pragma unroll
        for (int j = 0; j < 8; j++)
            #pragma unroll
            for (int r = 0; r < 4; r++) acc[i][j][r] = 0.f;

    int r8 = lane & 7, seg = lane >> 3;
    int a_row = (seg & 1) * 8 + r8;
    int a_kb  = (seg >> 1) * 16;
    int b_row = (seg >> 1) * 8 + r8;
    int b_kb  = (seg & 1) * 16;

    load_stage(0, 0);

    for (int i = 0; i < NC; i++) {
        if (i + 1 < NC) {
            load_stage((i + 1) & 1, (i + 1) << 5);
            asm volatile("cp.async.wait_group 1;");
        } else {
            asm volatile("cp.async.wait_group 0;");
        }
        __syncthreads();

        uint32_t base = sb + (i & 1) * STAGEB;
        #pragma unroll
        for (int ks = 0; ks < 2; ks++) {
            int kb = ks * 32;
            uint32_t ah[2][4], al[2][4], bh[4][4], bl[4][4];
            #pragma unroll
            for (int mi = 0; mi < 2; mi++) {
                uint32_t ad = base + (wr * 32 + mi * 16 + a_row) * PADB + kb + a_kb;
                ldmx4(ah[mi], ad);
                ldmx4(al[mi], ad + TILEB);
            }
            #pragma unroll
            for (int nj = 0; nj < 4; nj++) {
                uint32_t bd = base + 2 * TILEB + (wc * 64 + nj * 16 + b_row) * PADB + kb + b_kb;
                ldmx4(bh[nj], bd);
                ldmx4(bl[nj], bd + TILEB);
            }
            #pragma unroll
            for (int mi = 0; mi < 2; mi++)
                #pragma unroll
                for (int nt = 0; nt < 8; nt++) {
                    int nj = nt >> 1, hf = (nt & 1) * 2;
                    mma16816(acc[mi][nt], ah[mi], bh[nj][hf], bh[nj][hf + 1]);
                    mma16816(acc[mi][nt], ah[mi], bl[nj][hf], bl[nj][hf + 1]);
                    mma16816(acc[mi][nt], al[mi], bh[nj][hf], bh[nj][hf + 1]);
                }
        }
        __syncthreads();
    }

    int brow = blockIdx.y * 128 + wr * 32 + (lane >> 2);
    int bcol = blockIdx.x * 128 + wc * 64 + (lane & 3) * 2;
    #pragma unroll
    for (int mi = 0; mi < 2; mi++)
        #pragma unroll
        for (int nt = 0; nt < 8; nt++)
            #pragma unroll
            for (int rh = 0; rh < 2; rh++) {
                int rr = brow + mi * 16 + rh * 8;
                int cc = bcol + nt * 8;
                float v0 = acc[mi][nt][rh * 2 + 0];
                float v1 = acc[mi][nt][rh * 2 + 1];
                if (bias) { v0 += __ldg(bias + cc); v1 += __ldg(bias + cc + 1); }
                size_t ci = (size_t)blockIdx.z * sC + (size_t)rr * ldc + cc;
                if (Cf) *(float2*)(Cf + ci) = make_float2(v0, v1);
                if (Ch) {
                    bf16 h0, l0, h1, l1;
                    split_bf16(v0, h0, l0); split_bf16(v1, h1, l1);
                    *(__nv_bfloat162*)(Ch + ci) = __nv_bfloat162(h0, h1);
                    *(__nv_bfloat162*)(Cl + ci) = __nv_bfloat162(l0, l1);
                }
            }
}

// ---------------- fused flash attention ----------------
// grid (36 q-tiles, 12 heads), 128 threads. Q tile 64x128, KV blocks of 64.
#define QPAD  272
#define KPAD  272
#define VPAD  144
#define QTB   (64 * QPAD)          // 17408
#define KTB   (64 * KPAD)          // 17408
#define VTB   (128 * VPAD)         // 18432
#define STGB  (2 * KTB + 2 * VTB)  // 71680
#define FSMEM (2 * QTB + 2 * STGB) // 178176

__global__ __launch_bounds__(128, 1)
void flash_attn(const bf16* __restrict__ Qh_, const bf16* __restrict__ Ql_,
                const bf16* __restrict__ Kh_, const bf16* __restrict__ Kl_,
                const bf16* __restrict__ Vh_, const bf16* __restrict__ Vl_,
                bf16* __restrict__ Oh_, bf16* __restrict__ Ol_)
{
    extern __shared__ char smem[];
    uint32_t sb = smem_u32(smem);
    int tid = threadIdx.x, wid = tid >> 5, lane = tid & 31;
    int h = blockIdx.y;
    int q0 = blockIdx.x * 64;

    const bf16* Qhb = Qh_ + ((size_t)h * S_ + q0) * D_;
    const bf16* Qlb = Ql_ + ((size_t)h * S_ + q0) * D_;
    const bf16* Khb = Kh_ + (size_t)h * S_ * D_;
    const bf16* Klb = Kl_ + (size_t)h * S_ * D_;
    const bf16* Vhb = Vh_ + (size_t)h * D_ * S_;
    const bf16* Vlb = Vl_ + (size_t)h * D_ * S_;

    const uint32_t Qs = sb, STG0 = sb + 2 * QTB;

    // Q load (64 rows x 256B, hi+lo)
    #pragma unroll
    for (int i = 0; i < 8; i++) {
        int c = tid + (i << 7);
        int row = c >> 4, ch = c & 15;
        cp16(Qs + row * QPAD + ch * 16,        (const char*)Qhb + (size_t)row * 256 + ch * 16);
        cp16(Qs + QTB + row * QPAD + ch * 16,  (const char*)Qlb + (size_t)row * 256 + ch * 16);
    }
    // stage loader
    auto load_stage = [&](int st, int blk) {
        uint32_t s0 = STG0 + st * STGB;
        const char* kh = (const char*)(Khb + (size_t)blk * 64 * D_);
        const char* kl = (const char*)(Klb + (size_t)blk * 64 * D_);
        #pragma unroll
        for (int i = 0; i < 8; i++) {
            int c = tid + (i << 7);
            int row = c >> 4, ch = c & 15;
            cp16(s0 + row * KPAD + ch * 16,       kh + (size_t)row * 256 + ch * 16);
            cp16(s0 + KTB + row * KPAD + ch * 16, kl + (size_t)row * 256 + ch * 16);
        }
        const char* vh = (const char*)(Vhb + (size_t)blk * 64);
        const char* vl = (const char*)(Vlb + (size_t)blk * 64);
        #pragma unroll
        for (int i = 0; i < 8; i++) {
            int c = tid + (i << 7);
            int row = c >> 3, ch = c & 7;
            cp16(s0 + 2 * KTB + row * VPAD + ch * 16,       vh + (size_t)row * S_ * 2 + ch * 16);
            cp16(s0 + 2 * KTB + VTB + row * VPAD + ch * 16, vl + (size_t)row * S_ * 2 + ch * 16);
        }
        asm volatile("cp.async.commit_group;");
    };
    load_stage(0, 0);

    int r8 = lane & 7, seg = lane >> 3;
    int a_row = (seg & 1) * 8 + r8;
    int a_kb  = (seg >> 1) * 16;
    int b_row = (seg >> 1) * 8 + r8;
    int b_kb  = (seg & 1) * 16;

    float o[16][4];
    #pragma unroll
    for (int t = 0; t < 16; t++)
        #pragma unroll
        for (int r = 0; r < 4; r++) o[t][r] = 0.f;
    float m0 = -1e30f, m1 = -1e30f, l0 = 0.f, l1 = 0.f;
    const float sc = 0.08838834764831845f;

    const int NB = S_ / 64;   // 36
    for (int blk = 0; blk < NB; blk++) {
        if (blk + 1 < NB) {
            load_stage((blk + 1) & 1, blk + 1);
            asm volatile("cp.async.wait_group 1;");
        } else {
            asm volatile("cp.async.wait_group 0;");
        }
        __syncthreads();

        uint32_t Ks = STG0 + (blk & 1) * STGB;
        uint32_t Vs = Ks + 2 * KTB;

        // ---- S = Q K^T (16 x 64 per warp) ----
        float st[8][4];
        #pragma unroll
        for (int t = 0; t < 8; t++)
            #pragma unroll
            for (int r = 0; r < 4; r++) st[t][r] = 0.f;

        #pragma unroll
        for (int ks = 0; ks < 8; ks++) {
            int kb = ks * 32;
            uint32_t qh[4], ql[4], kh[4][4], kl[4][4];
            uint32_t qa = Qs + (wid * 16 + a_row) * QPAD + kb + a_kb;
            ldmx4(qh, qa);
            ldmx4(ql, qa + QTB);
            #pragma unroll
            for (int nj = 0; nj < 4; nj++) {
                uint32_t ka = Ks + (nj * 16 + b_row) * KPAD + kb + b_kb;
                ldmx4(kh[nj], ka);
                ldmx4(kl[nj], ka + KTB);
            }
            #pragma unroll
            for (int nt = 0; nt < 8; nt++) {
                int nj = nt >> 1, hf = (nt & 1) * 2;
                mma16816(st[nt], qh, kh[nj][hf], kh[nj][hf + 1]);
                mma16816(st[nt], qh, kl[nj][hf], kl[nj][hf + 1]);
                mma16816(st[nt], ql, kh[nj][hf], kh[nj][hf + 1]);
            }
        }

        // ---- online softmax (warp-local rows) ----
        float bm0 = -1e30f, bm1 = -1e30f;
        #pragma unroll
        for (int t = 0; t < 8; t++) {
            bm0 = fmaxf(bm0, fmaxf(st[t][0], st[t][1]));
            bm1 = fmaxf(bm1, fmaxf(st[t][2], st[t][3]));
        }
        #pragma unroll
        for (int off = 1; off <= 2; off <<= 1) {
            bm0 = fmaxf(bm0, __shfl_xor_sync(0xffffffffu, bm0, off));
            bm1 = fmaxf(bm1, __shfl_xor_sync(0xffffffffu, bm1, off));
        }
        float nm0 = fmaxf(m0, bm0), nm1 = fmaxf(m1, bm1);
        float al0 = __expf((m0 - nm0) * sc), al1 = __expf((m1 - nm1) * sc);
        float ps0 = 0.f, ps1 = 0.f;
        #pragma unroll
        for (int t = 0; t < 8; t++) {
            st[t][0] = __expf((st[t][0] - nm0) * sc);
            st[t][1] = __expf((st[t][1] - nm0) * sc);
            st[t][2] = __expf((st[t][2] - nm1) * sc);
            st[t][3] = __expf((st[t][3] - nm1) * sc);
            ps0 += st[t][0] + st[t][1];
            ps1 += st[t][2] + st[t][3];
        }
        #pragma unroll
        for (int off = 1; off <= 2; off <<= 1) {
            ps0 += __shfl_xor_sync(0xffffffffu, ps0, off);
            ps1 += __shfl_xor_sync(0xffffffffu, ps1, off);
        }
        l0 = l0 * al0 + ps0;
        l1 = l1 * al1 + ps1;
        m0 = nm0; m1 = nm1;
        #pragma unroll
        for (int t = 0; t < 16; t++) {
            o[t][0] *= al0; o[t][1] *= al0;
            o[t][2] *= al1; o[t][3] *= al1;
        }

        // ---- O += P V (P from S frags, hi/lo split in registers) ----
        #pragma unroll
        for (int g = 0; g < 4; g++) {
            uint32_t aph[4], apl[4];
            #pragma unroll
            for (int half = 0; half < 2; half++) {
                float* s0 = st[2 * g + half];
                aph[2 * half + 0] = pack_hi2(s0[0], s0[1], apl[2 * half + 0]);
                aph[2 * half + 1] = pack_hi2(s0[2], s0[3], apl[2 * half + 1]);
            }
            #pragma unroll
            for (int nj = 0; nj < 8; nj++) {
                uint32_t vh[4], vl[4];
                uint32_t va = Vs + (nj * 16 + b_row) * VPAD + g * 32 + b_kb;
                ldmx4(vh, va);
                ldmx4(vl, va + VTB);
                #pragma unroll
                for (int half = 0; half < 2; half++) {
                    int t = nj * 2 + half;
                    int hf = half * 2;
                    mma16816(o[t], aph, vh[hf], vh[hf + 1]);
                    mma16816(o[t], apl, vh[hf], vh[hf + 1]);
                    mma16816(o[t], aph, vl[hf], vl[hf + 1]);
                }
            }
        }
        __syncthreads();
    }

    // ---- finalize + write O hi/lo at [s][h*128+d] ----
    float i0 = 1.f / l0, i1 = 1.f / l1;
    int sr0 = q0 + wid * 16 + (lane >> 2);
    #pragma unroll
    for (int t = 0; t < 16; t++) {
        int cc = h * 128 + t * 8 + (lane & 3) * 2;
        {
            float v0 = o[t][0] * i0, v1 = o[t][1] * i0;
            bf16 h0, lo0, h1, lo1;
            split_bf16(v0, h0, lo0); split_bf16(v1, h1, lo1);
            size_t ci = (size_t)sr0 * DX_ + cc;
            *(__nv_bfloat162*)(Oh_ + ci) = __nv_bfloat162(h0, h1);
            *(__nv_bfloat162*)(Ol_ + ci) = __nv_bfloat162(lo0, lo1);
        }
        {
            float v0 = o[t][2] * i1, v1 = o[t][3] * i1;
            bf16 h0, lo0, h1, lo1;
            split_bf16(v0, h0, lo0); split_bf16(v1, h1, lo1);
            size_t ci = (size_t)(sr0 + 8) * DX_ + cc;
            *(__nv_bfloat162*)(Oh_ + ci) = __nv_bfloat162(h0, h1);
            *(__nv_bfloat162*)(Ol_ + ci) = __nv_bfloat162(lo0, lo1);
        }
    }
}

// ---------------- RMSNorm + modulation, split hi/lo ----------------
__global__ void rms_mod_split(const float* __restrict__ X, const float* __restrict__ sc,
                              bf16* __restrict__ oh, bf16* __restrict__ ol, int Dm, float eps) {
    __shared__ float sbuf[32];
    size_t row = blockIdx.x;
    const float* xr = X + row * Dm;
    float ss = 0.f;
    for (int i = threadIdx.x; i < Dm; i += blockDim.x) { float t = xr[i]; ss += t * t; }
    ss = block_red(ss, sbuf, false);
    float r = rsqrtf(ss / (float)Dm + eps);
    for (int i = threadIdx.x; i < Dm; i += blockDim.x) {
        float v = xr[i] * r * (1.f + sc[i]);
        bf16 h, l; split_bf16(v, h, l);
        oh[row * Dm + i] = h; ol[row * Dm + i] = l;
    }
}

// ---------------- weight transpose + split ----------------
__global__ void wconv(const float* __restrict__ W, bf16* __restrict__ Th, bf16* __restrict__ Tl,
                      int K, int N) {
    __shared__ float t[32][33];
    int n0 = blockIdx.x * 32, k0 = blockIdx.y * 32;
    int tx = threadIdx.x, ty = threadIdx.y;
    #pragma unroll
    for (int j = 0; j < 32; j += 8)
        t[ty + j][tx] = W[(size_t)(k0 + ty + j) * N + n0 + tx];
    __syncthreads();
    #pragma unroll
    for (int j = 0; j < 32; j += 8) {
        float v = t[tx][ty + j];
        size_t o = (size_t)(n0 + ty + j) * K + k0 + tx;
        bf16 h, l; split_bf16(v, h, l);
        Th[o] = h; Tl[o] = l;
    }
}

// ---------------- Q/K per-head RMSNorm + RoPE ----------------
__global__ void qkv_transform(const float* __restrict__ rope_cos, const float* __restrict__ rope_sin,
                              const float* __restrict__ qnx, const float* __restrict__ knx,
                              const float* __restrict__ qny, const float* __restrict__ kny) {
    __shared__ float sbuf[32];
    int s = blockIdx.x, h = blockIdx.y, d = threadIdx.x;
    bool isx = (s < NX);
    const float* base = isx ? (g_qkvx + (size_t)s * QKVN) : (g_qkvy + (size_t)(s - NX) * QKVN);
    int col = h * D_ + d;
    float q = base[col];
    float k = base[DX_ + col];

    float sq = block_red(q * q, sbuf, false);
    float sk = block_red(k * k, sbuf, false);
    float rq = rsqrtf(sq * (1.f / D_) + 1e-5f);
    float rk = rsqrtf(sk * (1.f / D_) + 1e-5f);
    float qn = q * rq * (isx ? qnx[d] : qny[d]);
    float kn = k * rk * (isx ? knx[d] : kny[d]);

    if (isx) {
        int i = d >> 1;
        size_t ridx = ((size_t)s * H_ + h) * (D_ / 2) + i;
        float c = rope_cos[ridx];
        float sn = rope_sin[ridx];
        float qp = __shfl_xor_sync(0xffffffffu, qn, 1);
        float kp = __shfl_xor_sync(0xffffffffu, kn, 1);
        if ((d & 1) == 0) { qn = qn * c - qp * sn;  kn = kn * c - kp * sn; }
        else              { qn = qp * sn + qn * c;  kn = kp * sn + kn * c; }
    }
    size_t o = ((size_t)h * S_ + s) * D_ + d;
    bf16 hh, ll;
    split_bf16(qn, hh, ll); g_Qh[o] = hh; g_Ql[o] = ll;
    split_bf16(kn, hh, ll); g_Kh[o] = hh; g_Kl[o] = ll;
}

// ---------------- V transpose to [H][D][S], split ----------------
__global__ void vconv() {
    __shared__ float t[32][33];
    int s0 = blockIdx.x * 32, d0 = blockIdx.y * 32, h = blockIdx.z;
    int tx = threadIdx.x, ty = threadIdx.y;
    #pragma unroll
    for (int j = 0; j < 32; j += 8) {
        int s = s0 + ty + j;
        const float* base = (s < NX) ? (g_qkvx + (size_t)s * QKVN)
                                     : (g_qkvy + (size_t)(s - NX) * QKVN);
        t[ty + j][tx] = base[2 * DX_ + h * D_ + d0 + tx];
    }
    __syncthreads();
    #pragma unroll
    for (int j = 0; j < 32; j += 8) {
        float v = t[tx][ty + j];
        size_t o = ((size_t)h * D_ + d0 + ty + j) * S_ + s0 + tx;
        bf16 hh, ll; split_bf16(v, hh, ll);
        g_Vth[o] = hh; g_Vtl[o] = ll;
    }
}

// ---------------- launch ----------------
extern "C" void kernel_launch(void* const* d_in, const int* in_sizes, int n_in,
                              void* d_out, int out_size)
{
    const float* x        = (const float*)d_in[0];
    const float* y        = (const float*)d_in[1];
    const float* scale_x  = (const float*)d_in[2];
    const float* scale_y  = (const float*)d_in[3];
    const float* rope_cos = (const float*)d_in[4];
    const float* rope_sin = (const float*)d_in[5];
    const float* Wqkv_x   = (const float*)d_in[6];
    const float* bqkv_x   = (const float*)d_in[7];
    const float* Wqkv_y   = (const float*)d_in[8];
    const float* bqkv_y   = (const float*)d_in[9];
    const float* q_norm_x = (const float*)d_in[10];
    const float* k_norm_x = (const float*)d_in[11];
    const float* q_norm_y = (const float*)d_in[12];
    const float* k_norm_y = (const float*)d_in[13];
    const float* Wproj_x  = (const float*)d_in[14];
    const float* bproj_x  = (const float*)d_in[15];
    const float* Wproj_y  = (const float*)d_in[16];
    const float* bproj_y  = (const float*)d_in[17];
    float* out = (float*)d_out;

    cudaFuncSetAttribute(mma_gemm, cudaFuncAttributeMaxDynamicSharedMemorySize, GSMEM);
    cudaFuncSetAttribute(flash_attn, cudaFuncAttributeMaxDynamicSharedMemorySize, FSMEM);

    float *qkvx, *qkvy;
    bf16 *xmh, *xml, *ymh, *yml, *wqxh, *wqxl, *wqyh, *wqyl, *wpxh, *wpxl, *wpyh, *wpyl;
    bf16 *Qh, *Ql, *Kh, *Kl, *Vth, *Vtl, *Oh, *Ol;
    cudaGetSymbolAddress((void**)&qkvx, g_qkvx);
    cudaGetSymbolAddress((void**)&qkvy, g_qkvy);
    cudaGetSymbolAddress((void**)&xmh,  g_xm_h);  cudaGetSymbolAddress((void**)&xml, g_xm_l);
    cudaGetSymbolAddress((void**)&ymh,  g_ym_h);  cudaGetSymbolAddress((void**)&yml, g_ym_l);
    cudaGetSymbolAddress((void**)&wqxh, g_WqxT_h); cudaGetSymbolAddress((void**)&wqxl, g_WqxT_l);
    cudaGetSymbolAddress((void**)&wqyh, g_WqyT_h); cudaGetSymbolAddress((void**)&wqyl, g_WqyT_l);
    cudaGetSymbolAddress((void**)&wpxh, g_WpxT_h); cudaGetSymbolAddress((void**)&wpxl, g_WpxT_l);
    cudaGetSymbolAddress((void**)&wpyh, g_WpyT_h); cudaGetSymbolAddress((void**)&wpyl, g_WpyT_l);
    cudaGetSymbolAddress((void**)&Qh, g_Qh);   cudaGetSymbolAddress((void**)&Ql, g_Ql);
    cudaGetSymbolAddress((void**)&Kh, g_Kh);   cudaGetSymbolAddress((void**)&Kl, g_Kl);
    cudaGetSymbolAddress((void**)&Vth, g_Vth); cudaGetSymbolAddress((void**)&Vtl, g_Vtl);
    cudaGetSymbolAddress((void**)&Oh, g_Oh);   cudaGetSymbolAddress((void**)&Ol, g_Ol);

    dim3 t328(32, 8);

    // 1) modulated RMSNorm (split) + weight transpose/split
    rms_mod_split<<<NX, 256>>>(x, scale_x, xmh, xml, DX_, 1e-6f);
    rms_mod_split<<<NY, 256>>>(y, scale_y, ymh, yml, DY_, 1e-6f);
    wconv<<<dim3(QKVN / 32, DX_ / 32), t328>>>(Wqkv_x, wqxh, wqxl, DX_, QKVN);
    wconv<<<dim3(QKVN / 32, DY_ / 32), t328>>>(Wqkv_y, wqyh, wqyl, DY_, QKVN);
    wconv<<<dim3(DX_ / 32,  DX_ / 32), t328>>>(Wproj_x, wpxh, wpxl, DX_, DX_);
    wconv<<<dim3(DY_ / 32,  DX_ / 32), t328>>>(Wproj_y, wpyh, wpyl, DX_, DY_);

    // 2) QKV projections (HMMA)
    mma_gemm<<<dim3(QKVN / 128, NX / 128, 1), 256, GSMEM>>>(
        xmh, xml, wqxh, wqxl, bqkv_x, qkvx, nullptr, nullptr,
        DX_, DX_, DX_, QKVN, 0, 0, 0);
    mma_gemm<<<dim3(QKVN / 128, NY / 128, 1), 256, GSMEM>>>(
        ymh, yml, wqyh, wqyl, bqkv_y, qkvy, nullptr, nullptr,
        DY_, DY_, DY_, QKVN, 0, 0, 0);

    // 3) Q/K transform + V transpose/split
    qkv_transform<<<dim3(S_, H_), D_>>>(rope_cos, rope_sin,
                                        q_norm_x, k_norm_x, q_norm_y, k_norm_y);
    vconv<<<dim3(S_ / 32, D_ / 32, H_), t328>>>();

    // 4-6) fused attention -> O hi/lo at [s][h*128+d]
    flash_attn<<<dim3(S_ / 64, H_), 128, FSMEM>>>(Qh, Ql, Kh, Kl, Vth, Vtl, Oh, Ol);

    // 7) output projections straight into d_out
    mma_gemm<<<dim3(DX_ / 128, NX / 128, 1), 256, GSMEM>>>(
        Oh, Ol, wpxh, wpxl, bproj_x, out, nullptr, nullptr,
        DX_, DX_, DX_, DX_, 0, 0, 0);
    mma_gemm<<<dim3(DY_ / 128, NY / 128, 1), 256, GSMEM>>>(
        Oh + (size_t)NX * DX_, Ol + (size_t)NX * DX_, wpyh, wpyl, bproj_y,
        out + (size_t)NX * DX_, nullptr, nullptr,
        DX_, DX_, DX_, DY_, 0, 0, 0);
}

// round 5
// speedup vs baseline: 2.9751x; 1.0816x over previous
#include <cuda_runtime.h>
#include <cuda_bf16.h>
#include <cstdint>
#include <math.h>

#define H_    12
#define D_    128
#define NX    2048
#define NY    256
#define S_    2304
#define DX_   1536
#define DY_   768
#define QKVN  4608

typedef __nv_bfloat16 bf16;

// ---------------- scratch (static device globals; no allocation) ----------------
__device__ __align__(256) float g_qkvx[(size_t)NX * QKVN];
__device__ __align__(256) float g_qkvy[(size_t)NY * QKVN];
__device__ __align__(256) bf16 g_xm_h[(size_t)NX * DX_],  g_xm_l[(size_t)NX * DX_];
__device__ __align__(256) bf16 g_ym_h[(size_t)NY * DY_],  g_ym_l[(size_t)NY * DY_];
__device__ __align__(256) bf16 g_WqxT_h[(size_t)QKVN * DX_], g_WqxT_l[(size_t)QKVN * DX_];
__device__ __align__(256) bf16 g_WqyT_h[(size_t)QKVN * DY_], g_WqyT_l[(size_t)QKVN * DY_];
__device__ __align__(256) bf16 g_WpxT_h[(size_t)DX_ * DX_],  g_WpxT_l[(size_t)DX_ * DX_];
__device__ __align__(256) bf16 g_WpyT_h[(size_t)DY_ * DX_],  g_WpyT_l[(size_t)DY_ * DX_];
__device__ __align__(256) bf16 g_Qh[(size_t)H_ * S_ * D_], g_Ql[(size_t)H_ * S_ * D_];
__device__ __align__(256) bf16 g_Kh[(size_t)H_ * S_ * D_], g_Kl[(size_t)H_ * S_ * D_];
__device__ __align__(256) bf16 g_Vth[(size_t)H_ * D_ * S_], g_Vtl[(size_t)H_ * D_ * S_];
__device__ __align__(256) bf16 g_Oh[(size_t)S_ * DX_],      g_Ol[(size_t)S_ * DX_];

// ---------------- small helpers ----------------
__device__ __forceinline__ float warp_sum(float v) {
    #pragma unroll
    for (int o = 16; o; o >>= 1) v += __shfl_xor_sync(0xffffffffu, v, o);
    return v;
}
__device__ __forceinline__ float warp_max(float v) {
    #pragma unroll
    for (int o = 16; o; o >>= 1) v = fmaxf(v, __shfl_xor_sync(0xffffffffu, v, o));
    return v;
}
__device__ float block_red(float v, float* sbuf, bool ismax) {
    v = ismax ? warp_max(v) : warp_sum(v);
    int w = threadIdx.x >> 5, nw = blockDim.x >> 5;
    if ((threadIdx.x & 31) == 0) sbuf[w] = v;
    __syncthreads();
    if (threadIdx.x < 32) {
        float t = (threadIdx.x < nw) ? sbuf[threadIdx.x] : (ismax ? -1e30f : 0.f);
        t = ismax ? warp_max(t) : warp_sum(t);
        if (threadIdx.x == 0) sbuf[0] = t;
    }
    __syncthreads();
    float r = sbuf[0];
    __syncthreads();
    return r;
}
__device__ __forceinline__ void split_bf16(float v, bf16& h, bf16& l) {
    h = __float2bfloat16(v);
    l = __float2bfloat16(v - __bfloat162float(h));
}
__device__ __forceinline__ uint32_t pack_hi2(float a, float b, uint32_t& lo) {
    bf16 h0, l0, h1, l1;
    split_bf16(a, h0, l0); split_bf16(b, h1, l1);
    __nv_bfloat162 hp(h0, h1), lp(l0, l1);
    lo = *(uint32_t*)&lp;
    return *(uint32_t*)&hp;
}
__device__ __forceinline__ uint32_t smem_u32(const void* p) {
    return (uint32_t)__cvta_generic_to_shared(p);
}
__device__ __forceinline__ void cp16(uint32_t s, const void* g) {
    asm volatile("cp.async.cg.shared.global [%0], [%1], 16;" :: "r"(s), "l"(g));
}
__device__ __forceinline__ void ldmx4(uint32_t* r, uint32_t a) {
    asm volatile("ldmatrix.sync.aligned.m8n8.x4.shared.b16 {%0,%1,%2,%3}, [%4];"
                 : "=r"(r[0]), "=r"(r[1]), "=r"(r[2]), "=r"(r[3]) : "r"(a));
}
__device__ __forceinline__ void mma16816(float* c, const uint32_t* a, uint32_t b0, uint32_t b1) {
    asm volatile(
        "mma.sync.aligned.m16n8k16.row.col.f32.bf16.bf16.f32 "
        "{%0,%1,%2,%3}, {%4,%5,%6,%7}, {%8,%9}, {%0,%1,%2,%3};"
        : "+f"(c[0]), "+f"(c[1]), "+f"(c[2]), "+f"(c[3])
        : "r"(a[0]), "r"(a[1]), "r"(a[2]), "r"(a[3]), "r"(b0), "r"(b1));
}

// ---------------- bf16x3 HMMA GEMM (QKV + proj) ----------------
#define PADB   80
#define TILEB  (128 * PADB)
#define STAGEB (4 * TILEB)
#define GSMEM  (2 * STAGEB)

__global__ __launch_bounds__(256, 2)
void mma_gemm(const bf16* __restrict__ Ah, const bf16* __restrict__ Al,
              const bf16* __restrict__ Bh, const bf16* __restrict__ Bl,
              const float* __restrict__ bias,
              float* __restrict__ Cf, bf16* __restrict__ Ch, bf16* __restrict__ Cl,
              int K, int lda, int ldb, int ldc,
              long sA, long sB, long sC)
{
    extern __shared__ char smem[];
    uint32_t sb = smem_u32(smem);
    int tid = threadIdx.x, wid = tid >> 5, lane = tid & 31;
    int wr = wid >> 1, wc = wid & 1;

    const bf16* pAh = Ah + (size_t)blockIdx.z * sA + (size_t)blockIdx.y * 128 * lda;
    const bf16* pAl = Al + (size_t)blockIdx.z * sA + (size_t)blockIdx.y * 128 * lda;
    const bf16* pBh = Bh + (size_t)blockIdx.z * sB + (size_t)blockIdx.x * 128 * ldb;
    const bf16* pBl = Bl + (size_t)blockIdx.z * sB + (size_t)blockIdx.x * 128 * ldb;

    const int NC = K >> 5;

    auto load_stage = [&](int st, int k0) {
        uint32_t s0 = sb + st * STAGEB;
        const bf16* srcs[4] = {pAh, pAl, pBh, pBl};
        #pragma unroll
        for (int t = 0; t < 4; t++) {
            int ldt = (t < 2) ? lda : ldb;
            const char* gb = (const char*)srcs[t] + (size_t)k0 * 2;
            #pragma unroll
            for (int i = 0; i < 2; i++) {
                int idx = tid + (i << 8);
                int row = idx >> 2, ch = idx & 3;
                cp16(s0 + t * TILEB + row * PADB + ch * 16,
                     gb + (size_t)row * ldt * 2 + ch * 16);
            }
        }
        asm volatile("cp.async.commit_group;");
    };

    float acc[2][8][4];
    #pragma unroll
    for (int i = 0; i < 2; i++)
        #pragma unroll
        for (int j = 0; j < 8; j++)
            #pragma unroll
            for (int r = 0; r < 4; r++) acc[i][j][r] = 0.f;

    int r8 = lane & 7, seg = lane >> 3;
    int a_row = (seg & 1) * 8 + r8;
    int a_kb  = (seg >> 1) * 16;
    int b_row = (seg >> 1) * 8 + r8;
    int b_kb  = (seg & 1) * 16;

    load_stage(0, 0);

    for (int i = 0; i < NC; i++) {
        if (i + 1 < NC) {
            load_stage((i + 1) & 1, (i + 1) << 5);
            asm volatile("cp.async.wait_group 1;");
        } else {
            asm volatile("cp.async.wait_group 0;");
        }
        __syncthreads();

        uint32_t base = sb + (i & 1) * STAGEB;
        #pragma unroll
        for (int ks = 0; ks < 2; ks++) {
            int kb = ks * 32;
            uint32_t ah[2][4], al[2][4], bh[4][4], bl[4][4];
            #pragma unroll
            for (int mi = 0; mi < 2; mi++) {
                uint32_t ad = base + (wr * 32 + mi * 16 + a_row) * PADB + kb + a_kb;
                ldmx4(ah[mi], ad);
                ldmx4(al[mi], ad + TILEB);
            }
            #pragma unroll
            for (int nj = 0; nj < 4; nj++) {
                uint32_t bd = base + 2 * TILEB + (wc * 64 + nj * 16 + b_row) * PADB + kb + b_kb;
                ldmx4(bh[nj], bd);
                ldmx4(bl[nj], bd + TILEB);
            }
            #pragma unroll
            for (int mi = 0; mi < 2; mi++)
                #pragma unroll
                for (int nt = 0; nt < 8; nt++) {
                    int nj = nt >> 1, hf = (nt & 1) * 2;
                    mma16816(acc[mi][nt], ah[mi], bh[nj][hf], bh[nj][hf + 1]);
                    mma16816(acc[mi][nt], ah[mi], bl[nj][hf], bl[nj][hf + 1]);
                    mma16816(acc[mi][nt], al[mi], bh[nj][hf], bh[nj][hf + 1]);
                }
        }
        __syncthreads();
    }

    int brow = blockIdx.y * 128 + wr * 32 + (lane >> 2);
    int bcol = blockIdx.x * 128 + wc * 64 + (lane & 3) * 2;
    #pragma unroll
    for (int mi = 0; mi < 2; mi++)
        #pragma unroll
        for (int nt = 0; nt < 8; nt++)
            #pragma unroll
            for (int rh = 0; rh < 2; rh++) {
                int rr = brow + mi * 16 + rh * 8;
                int cc = bcol + nt * 8;
                float v0 = acc[mi][nt][rh * 2 + 0];
                float v1 = acc[mi][nt][rh * 2 + 1];
                if (bias) { v0 += __ldg(bias + cc); v1 += __ldg(bias + cc + 1); }
                size_t ci = (size_t)blockIdx.z * sC + (size_t)rr * ldc + cc;
                if (Cf) *(float2*)(Cf + ci) = make_float2(v0, v1);
                if (Ch) {
                    bf16 h0, l0, h1, l1;
                    split_bf16(v0, h0, l0); split_bf16(v1, h1, l1);
                    *(__nv_bfloat162*)(Ch + ci) = __nv_bfloat162(h0, h1);
                    *(__nv_bfloat162*)(Cl + ci) = __nv_bfloat162(l0, l1);
                }
            }
}

// ---------------- fused flash attention ----------------
#define QPAD  272
#define KPAD  272
#define VPAD  144
#define QTB   (64 * QPAD)
#define KTB   (64 * KPAD)
#define VTB   (128 * VPAD)
#define STGB  (2 * KTB + 2 * VTB)
#define FSMEM (2 * QTB + 2 * STGB)

__global__ __launch_bounds__(128, 1)
void flash_attn(const bf16* __restrict__ Qh_, const bf16* __restrict__ Ql_,
                const bf16* __restrict__ Kh_, const bf16* __restrict__ Kl_,
                const bf16* __restrict__ Vh_, const bf16* __restrict__ Vl_,
                bf16* __restrict__ Oh_, bf16* __restrict__ Ol_)
{
    extern __shared__ char smem[];
    uint32_t sb = smem_u32(smem);
    int tid = threadIdx.x, wid = tid >> 5, lane = tid & 31;
    int h = blockIdx.y;
    int q0 = blockIdx.x * 64;

    const bf16* Qhb = Qh_ + ((size_t)h * S_ + q0) * D_;
    const bf16* Qlb = Ql_ + ((size_t)h * S_ + q0) * D_;
    const bf16* Khb = Kh_ + (size_t)h * S_ * D_;
    const bf16* Klb = Kl_ + (size_t)h * S_ * D_;
    const bf16* Vhb = Vh_ + (size_t)h * D_ * S_;
    const bf16* Vlb = Vl_ + (size_t)h * D_ * S_;

    const uint32_t Qs = sb, STG0 = sb + 2 * QTB;

    #pragma unroll
    for (int i = 0; i < 8; i++) {
        int c = tid + (i << 7);
        int row = c >> 4, ch = c & 15;
        cp16(Qs + row * QPAD + ch * 16,        (const char*)Qhb + (size_t)row * 256 + ch * 16);
        cp16(Qs + QTB + row * QPAD + ch * 16,  (const char*)Qlb + (size_t)row * 256 + ch * 16);
    }
    auto load_stage = [&](int st, int blk) {
        uint32_t s0 = STG0 + st * STGB;
        const char* kh = (const char*)(Khb + (size_t)blk * 64 * D_);
        const char* kl = (const char*)(Klb + (size_t)blk * 64 * D_);
        #pragma unroll
        for (int i = 0; i < 8; i++) {
            int c = tid + (i << 7);
            int row = c >> 4, ch = c & 15;
            cp16(s0 + row * KPAD + ch * 16,       kh + (size_t)row * 256 + ch * 16);
            cp16(s0 + KTB + row * KPAD + ch * 16, kl + (size_t)row * 256 + ch * 16);
        }
        const char* vh = (const char*)(Vhb + (size_t)blk * 64);
        const char* vl = (const char*)(Vlb + (size_t)blk * 64);
        #pragma unroll
        for (int i = 0; i < 8; i++) {
            int c = tid + (i << 7);
            int row = c >> 3, ch = c & 7;
            cp16(s0 + 2 * KTB + row * VPAD + ch * 16,       vh + (size_t)row * S_ * 2 + ch * 16);
            cp16(s0 + 2 * KTB + VTB + row * VPAD + ch * 16, vl + (size_t)row * S_ * 2 + ch * 16);
        }
        asm volatile("cp.async.commit_group;");
    };
    load_stage(0, 0);

    int r8 = lane & 7, seg = lane >> 3;
    int a_row = (seg & 1) * 8 + r8;
    int a_kb  = (seg >> 1) * 16;
    int b_row = (seg >> 1) * 8 + r8;
    int b_kb  = (seg & 1) * 16;

    float o[16][4];
    #pragma unroll
    for (int t = 0; t < 16; t++)
        #pragma unroll
        for (int r = 0; r < 4; r++) o[t][r] = 0.f;
    float m0 = -1e30f, m1 = -1e30f, l0 = 0.f, l1 = 0.f;
    const float sc = 0.08838834764831845f;

    const int NB = S_ / 64;
    for (int blk = 0; blk < NB; blk++) {
        if (blk + 1 < NB) {
            load_stage((blk + 1) & 1, blk + 1);
            asm volatile("cp.async.wait_group 1;");
        } else {
            asm volatile("cp.async.wait_group 0;");
        }
        __syncthreads();

        uint32_t Ks = STG0 + (blk & 1) * STGB;
        uint32_t Vs = Ks + 2 * KTB;

        float st[8][4];
        #pragma unroll
        for (int t = 0; t < 8; t++)
            #pragma unroll
            for (int r = 0; r < 4; r++) st[t][r] = 0.f;

        #pragma unroll
        for (int ks = 0; ks < 8; ks++) {
            int kb = ks * 32;
            uint32_t qh[4], ql[4], kh[4][4], kl[4][4];
            uint32_t qa = Qs + (wid * 16 + a_row) * QPAD + kb + a_kb;
            ldmx4(qh, qa);
            ldmx4(ql, qa + QTB);
            #pragma unroll
            for (int nj = 0; nj < 4; nj++) {
                uint32_t ka = Ks + (nj * 16 + b_row) * KPAD + kb + b_kb;
                ldmx4(kh[nj], ka);
                ldmx4(kl[nj], ka + KTB);
            }
            #pragma unroll
            for (int nt = 0; nt < 8; nt++) {
                int nj = nt >> 1, hf = (nt & 1) * 2;
                mma16816(st[nt], qh, kh[nj][hf], kh[nj][hf + 1]);
                mma16816(st[nt], qh, kl[nj][hf], kl[nj][hf + 1]);
                mma16816(st[nt], ql, kh[nj][hf], kh[nj][hf + 1]);
            }
        }

        float bm0 = -1e30f, bm1 = -1e30f;
        #pragma unroll
        for (int t = 0; t < 8; t++) {
            bm0 = fmaxf(bm0, fmaxf(st[t][0], st[t][1]));
            bm1 = fmaxf(bm1, fmaxf(st[t][2], st[t][3]));
        }
        #pragma unroll
        for (int off = 1; off <= 2; off <<= 1) {
            bm0 = fmaxf(bm0, __shfl_xor_sync(0xffffffffu, bm0, off));
            bm1 = fmaxf(bm1, __shfl_xor_sync(0xffffffffu, bm1, off));
        }
        float nm0 = fmaxf(m0, bm0), nm1 = fmaxf(m1, bm1);
        float al0 = __expf((m0 - nm0) * sc), al1 = __expf((m1 - nm1) * sc);
        float ps0 = 0.f, ps1 = 0.f;
        #pragma unroll
        for (int t = 0; t < 8; t++) {
            st[t][0] = __expf((st[t][0] - nm0) * sc);
            st[t][1] = __expf((st[t][1] - nm0) * sc);
            st[t][2] = __expf((st[t][2] - nm1) * sc);
            st[t][3] = __expf((st[t][3] - nm1) * sc);
            ps0 += st[t][0] + st[t][1];
            ps1 += st[t][2] + st[t][3];
        }
        #pragma unroll
        for (int off = 1; off <= 2; off <<= 1) {
            ps0 += __shfl_xor_sync(0xffffffffu, ps0, off);
            ps1 += __shfl_xor_sync(0xffffffffu, ps1, off);
        }
        l0 = l0 * al0 + ps0;
        l1 = l1 * al1 + ps1;
        m0 = nm0; m1 = nm1;
        #pragma unroll
        for (int t = 0; t < 16; t++) {
            o[t][0] *= al0; o[t][1] *= al0;
            o[t][2] *= al1; o[t][3] *= al1;
        }

        #pragma unroll
        for (int g = 0; g < 4; g++) {
            uint32_t aph[4], apl[4];
            #pragma unroll
            for (int half = 0; half < 2; half++) {
                float* s0 = st[2 * g + half];
                aph[2 * half + 0] = pack_hi2(s0[0], s0[1], apl[2 * half + 0]);
                aph[2 * half + 1] = pack_hi2(s0[2], s0[3], apl[2 * half + 1]);
            }
            #pragma unroll
            for (int nj = 0; nj < 8; nj++) {
                uint32_t vh[4], vl[4];
                uint32_t va = Vs + (nj * 16 + b_row) * VPAD + g * 32 + b_kb;
                ldmx4(vh, va);
                ldmx4(vl, va + VTB);
                #pragma unroll
                for (int half = 0; half < 2; half++) {
                    int t = nj * 2 + half;
                    int hf = half * 2;
                    mma16816(o[t], aph, vh[hf], vh[hf + 1]);
                    mma16816(o[t], apl, vh[hf], vh[hf + 1]);
                    mma16816(o[t], aph, vl[hf], vl[hf + 1]);
                }
            }
        }
        __syncthreads();
    }

    float i0 = 1.f / l0, i1 = 1.f / l1;
    int sr0 = q0 + wid * 16 + (lane >> 2);
    #pragma unroll
    for (int t = 0; t < 16; t++) {
        int cc = h * 128 + t * 8 + (lane & 3) * 2;
        {
            float v0 = o[t][0] * i0, v1 = o[t][1] * i0;
            bf16 h0, lo0, h1, lo1;
            split_bf16(v0, h0, lo0); split_bf16(v1, h1, lo1);
            size_t ci = (size_t)sr0 * DX_ + cc;
            *(__nv_bfloat162*)(Oh_ + ci) = __nv_bfloat162(h0, h1);
            *(__nv_bfloat162*)(Ol_ + ci) = __nv_bfloat162(lo0, lo1);
        }
        {
            float v0 = o[t][2] * i1, v1 = o[t][3] * i1;
            bf16 h0, lo0, h1, lo1;
            split_bf16(v0, h0, lo0); split_bf16(v1, h1, lo1);
            size_t ci = (size_t)(sr0 + 8) * DX_ + cc;
            *(__nv_bfloat162*)(Oh_ + ci) = __nv_bfloat162(h0, h1);
            *(__nv_bfloat162*)(Ol_ + ci) = __nv_bfloat162(lo0, lo1);
        }
    }
}

// ---------------- RMSNorm + modulation, split hi/lo ----------------
__global__ void rms_mod_split(const float* __restrict__ X, const float* __restrict__ sc,
                              bf16* __restrict__ oh, bf16* __restrict__ ol, int Dm, float eps) {
    __shared__ float sbuf[32];
    size_t row = blockIdx.x;
    const float* xr = X + row * Dm;
    float ss = 0.f;
    for (int i = threadIdx.x; i < Dm; i += blockDim.x) { float t = xr[i]; ss += t * t; }
    ss = block_red(ss, sbuf, false);
    float r = rsqrtf(ss / (float)Dm + eps);
    for (int i = threadIdx.x; i < Dm; i += blockDim.x) {
        float v = xr[i] * r * (1.f + sc[i]);
        bf16 h, l; split_bf16(v, h, l);
        oh[row * Dm + i] = h; ol[row * Dm + i] = l;
    }
}

// ---------------- dual weight transpose + split (z selects matrix) ----------------
__global__ void wconv2(const float* __restrict__ W0, bf16* __restrict__ Th0, bf16* __restrict__ Tl0,
                       int K0, int N0,
                       const float* __restrict__ W1, bf16* __restrict__ Th1, bf16* __restrict__ Tl1,
                       int K1, int N1) {
    const float* W; bf16 *Th, *Tl; int K, N;
    if (blockIdx.z == 0) { W = W0; Th = Th0; Tl = Tl0; K = K0; N = N0; }
    else                 { W = W1; Th = Th1; Tl = Tl1; K = K1; N = N1; }
    int n0 = blockIdx.x * 32, k0 = blockIdx.y * 32;
    if (n0 >= N || k0 >= K) return;
    __shared__ float t[32][33];
    int tx = threadIdx.x, ty = threadIdx.y;
    #pragma unroll
    for (int j = 0; j < 32; j += 8)
        t[ty + j][tx] = W[(size_t)(k0 + ty + j) * N + n0 + tx];
    __syncthreads();
    #pragma unroll
    for (int j = 0; j < 32; j += 8) {
        float v = t[tx][ty + j];
        size_t o = (size_t)(n0 + ty + j) * K + k0 + tx;
        bf16 h, l; split_bf16(v, h, l);
        Th[o] = h; Tl[o] = l;
    }
}

// ---------------- Q/K per-head RMSNorm + RoPE ----------------
__global__ void qkv_transform(const float* __restrict__ rope_cos, const float* __restrict__ rope_sin,
                              const float* __restrict__ qnx, const float* __restrict__ knx,
                              const float* __restrict__ qny, const float* __restrict__ kny) {
    __shared__ float sbuf[32];
    int s = blockIdx.x, h = blockIdx.y, d = threadIdx.x;
    bool isx = (s < NX);
    const float* base = isx ? (g_qkvx + (size_t)s * QKVN) : (g_qkvy + (size_t)(s - NX) * QKVN);
    int col = h * D_ + d;
    float q = base[col];
    float k = base[DX_ + col];

    float sq = block_red(q * q, sbuf, false);
    float sk = block_red(k * k, sbuf, false);
    float rq = rsqrtf(sq * (1.f / D_) + 1e-5f);
    float rk = rsqrtf(sk * (1.f / D_) + 1e-5f);
    float qn = q * rq * (isx ? qnx[d] : qny[d]);
    float kn = k * rk * (isx ? knx[d] : kny[d]);

    if (isx) {
        int i = d >> 1;
        size_t ridx = ((size_t)s * H_ + h) * (D_ / 2) + i;
        float c = rope_cos[ridx];
        float sn = rope_sin[ridx];
        float qp = __shfl_xor_sync(0xffffffffu, qn, 1);
        float kp = __shfl_xor_sync(0xffffffffu, kn, 1);
        if ((d & 1) == 0) { qn = qn * c - qp * sn;  kn = kn * c - kp * sn; }
        else              { qn = qp * sn + qn * c;  kn = kp * sn + kn * c; }
    }
    size_t o = ((size_t)h * S_ + s) * D_ + d;
    bf16 hh, ll;
    split_bf16(qn, hh, ll); g_Qh[o] = hh; g_Ql[o] = ll;
    split_bf16(kn, hh, ll); g_Kh[o] = hh; g_Kl[o] = ll;
}

// ---------------- V transpose to [H][D][S], split ----------------
__global__ void vconv() {
    __shared__ float t[32][33];
    int s0 = blockIdx.x * 32, d0 = blockIdx.y * 32, h = blockIdx.z;
    int tx = threadIdx.x, ty = threadIdx.y;
    #pragma unroll
    for (int j = 0; j < 32; j += 8) {
        int s = s0 + ty + j;
        const float* base = (s < NX) ? (g_qkvx + (size_t)s * QKVN)
                                     : (g_qkvy + (size_t)(s - NX) * QKVN);
        t[ty + j][tx] = base[2 * DX_ + h * D_ + d0 + tx];
    }
    __syncthreads();
    #pragma unroll
    for (int j = 0; j < 32; j += 8) {
        float v = t[tx][ty + j];
        size_t o = ((size_t)h * D_ + d0 + ty + j) * S_ + s0 + tx;
        bf16 hh, ll; split_bf16(v, hh, ll);
        g_Vth[o] = hh; g_Vtl[o] = ll;
    }
}

// ---------------- launch ----------------
extern "C" void kernel_launch(void* const* d_in, const int* in_sizes, int n_in,
                              void* d_out, int out_size)
{
    const float* x        = (const float*)d_in[0];
    const float* y        = (const float*)d_in[1];
    const float* scale_x  = (const float*)d_in[2];
    const float* scale_y  = (const float*)d_in[3];
    const float* rope_cos = (const float*)d_in[4];
    const float* rope_sin = (const float*)d_in[5];
    const float* Wqkv_x   = (const float*)d_in[6];
    const float* bqkv_x   = (const float*)d_in[7];
    const float* Wqkv_y   = (const float*)d_in[8];
    const float* bqkv_y   = (const float*)d_in[9];
    const float* q_norm_x = (const float*)d_in[10];
    const float* k_norm_x = (const float*)d_in[11];
    const float* q_norm_y = (const float*)d_in[12];
    const float* k_norm_y = (const float*)d_in[13];
    const float* Wproj_x  = (const float*)d_in[14];
    const float* bproj_x  = (const float*)d_in[15];
    const float* Wproj_y  = (const float*)d_in[16];
    const float* bproj_y  = (const float*)d_in[17];
    float* out = (float*)d_out;

    cudaFuncSetAttribute(mma_gemm, cudaFuncAttributeMaxDynamicSharedMemorySize, GSMEM);
    cudaFuncSetAttribute(flash_attn, cudaFuncAttributeMaxDynamicSharedMemorySize, FSMEM);

    float *qkvx, *qkvy;
    bf16 *xmh, *xml, *ymh, *yml, *wqxh, *wqxl, *wqyh, *wqyl, *wpxh, *wpxl, *wpyh, *wpyl;
    bf16 *Qh, *Ql, *Kh, *Kl, *Vth, *Vtl, *Oh, *Ol;
    cudaGetSymbolAddress((void**)&qkvx, g_qkvx);
    cudaGetSymbolAddress((void**)&qkvy, g_qkvy);
    cudaGetSymbolAddress((void**)&xmh,  g_xm_h);  cudaGetSymbolAddress((void**)&xml, g_xm_l);
    cudaGetSymbolAddress((void**)&ymh,  g_ym_h);  cudaGetSymbolAddress((void**)&yml, g_ym_l);
    cudaGetSymbolAddress((void**)&wqxh, g_WqxT_h); cudaGetSymbolAddress((void**)&wqxl, g_WqxT_l);
    cudaGetSymbolAddress((void**)&wqyh, g_WqyT_h); cudaGetSymbolAddress((void**)&wqyl, g_WqyT_l);
    cudaGetSymbolAddress((void**)&wpxh, g_WpxT_h); cudaGetSymbolAddress((void**)&wpxl, g_WpxT_l);
    cudaGetSymbolAddress((void**)&wpyh, g_WpyT_h); cudaGetSymbolAddress((void**)&wpyl, g_WpyT_l);
    cudaGetSymbolAddress((void**)&Qh, g_Qh);   cudaGetSymbolAddress((void**)&Ql, g_Ql);
    cudaGetSymbolAddress((void**)&Kh, g_Kh);   cudaGetSymbolAddress((void**)&Kl, g_Kl);
    cudaGetSymbolAddress((void**)&Vth, g_Vth); cudaGetSymbolAddress((void**)&Vtl, g_Vtl);
    cudaGetSymbolAddress((void**)&Oh, g_Oh);   cudaGetSymbolAddress((void**)&Ol, g_Ol);

    dim3 t328(32, 8);

    // 1-2) modulated RMSNorm (split)
    rms_mod_split<<<NX, 256>>>(x, scale_x, xmh, xml, DX_, 1e-6f);
    rms_mod_split<<<NY, 256>>>(y, scale_y, ymh, yml, DY_, 1e-6f);
    // 3) QKV weight transpose/split (x + y merged)
    wconv2<<<dim3(QKVN / 32, DX_ / 32, 2), t328>>>(
        Wqkv_x, wqxh, wqxl, DX_, QKVN,
        Wqkv_y, wqyh, wqyl, DY_, QKVN);
    // 4) proj weight transpose/split (x + y merged)
    wconv2<<<dim3(DX_ / 32, DX_ / 32, 2), t328>>>(
        Wproj_x, wpxh, wpxl, DX_, DX_,
        Wproj_y, wpyh, wpyl, DX_, DY_);

    // 5) QKV projection y (small, before x so x lands 6th for ncu)
    mma_gemm<<<dim3(QKVN / 128, NY / 128, 1), 256, GSMEM>>>(
        ymh, yml, wqyh, wqyl, bqkv_y, qkvy, nullptr, nullptr,
        DY_, DY_, DY_, QKVN, 0, 0, 0);
    // 6) QKV projection x  <-- profiled launch
    mma_gemm<<<dim3(QKVN / 128, NX / 128, 1), 256, GSMEM>>>(
        xmh, xml, wqxh, wqxl, bqkv_x, qkvx, nullptr, nullptr,
        DX_, DX_, DX_, QKVN, 0, 0, 0);

    // 7-8) Q/K transform + V transpose/split
    qkv_transform<<<dim3(S_, H_), D_>>>(rope_cos, rope_sin,
                                        q_norm_x, k_norm_x, q_norm_y, k_norm_y);
    vconv<<<dim3(S_ / 32, D_ / 32, H_), t328>>>();

    // 9) fused attention -> O hi/lo at [s][h*128+d]
    flash_attn<<<dim3(S_ / 64, H_), 128, FSMEM>>>(Qh, Ql, Kh, Kl, Vth, Vtl, Oh, Ol);

    // 10-11) output projections straight into d_out
    mma_gemm<<<dim3(DX_ / 128, NX / 128, 1), 256, GSMEM>>>(
        Oh, Ol, wpxh, wpxl, bproj_x, out, nullptr, nullptr,
        DX_, DX_, DX_, DX_, 0, 0, 0);
    mma_gemm<<<dim3(DY_ / 128, NY / 128, 1), 256, GSMEM>>>(
        Oh + (size_t)NX * DX_, Ol + (size_t)NX * DX_, wpyh, wpyl, bproj_y,
        out + (size_t)NX * DX_, nullptr, nullptr,
        DX_, DX_, DX_, DY_, 0, 0, 0);
}